// round 9
// baseline (speedup 1.0000x reference)
#include <cuda_runtime.h>
#include <cstring>

#define S_LEN 512
#define BATCH 64
#define IDIM  256
#define HID   512
#define ODIM  512    // 2*O

#define RSTR 68      // sred row stride in floats: 272B = 16B-aligned, conflict-free

// ---------------- scratch (static device globals; no allocation) -------------
__device__ float    g_hsT[(size_t)(S_LEN + 1) * 4 * HID * 16];  // [step][grp][k512][b16]
__device__ float    g_xT [(size_t)S_LEN * 4 * IDIM * 16];       // [s][grp][k256][b16]
__device__ unsigned g_blk[4 * 8 * 64];                          // per-(grp,block) counters

// ---------------- packed f32x2 FMA (full-rate fp32 on sm_100a) ---------------
__device__ __forceinline__ float2 ffma2(float2 a, float2 b, float2 c) {
#if defined(__CUDA_ARCH__) && (__CUDA_ARCH__ >= 1000)
    unsigned long long au, bu, cu, du;
    memcpy(&au, &a, 8); memcpy(&bu, &b, 8); memcpy(&cu, &c, 8);
    asm("fma.rn.f32x2 %0, %1, %2, %3;" : "=l"(du) : "l"(au), "l"(bu), "l"(cu));
    float2 d; memcpy(&d, &du, 8);
    return d;
#else
    return make_float2(fmaf(a.x, b.x, c.x), fmaf(a.y, b.y, c.y));
#endif
}

__device__ __forceinline__ void poll_ge(const unsigned* a, unsigned need) {
    unsigned v;
    do {
        asm volatile("ld.acquire.gpu.global.u32 %0, [%1];" : "=r"(v) : "l"(a) : "memory");
    } while (v < need);
}

__device__ __forceinline__ float fast_sigmoid(float x) {
    return __fdividef(1.f, 1.f + __expf(-x));
}
__device__ __forceinline__ float fast_tanh(float x) {
    return __fdividef(2.f, 1.f + __expf(-2.f * x)) - 1.f;
}

// =============================================================================
// Prologue: x[b][s][k] -> g_xT[s][grp][k][b16]  (smem transpose, coalesced)
// =============================================================================
__global__ __launch_bounds__(256)
void transpose_x(const float* __restrict__ x)
{
    __shared__ float ts[16 * 260];
    const int tid = threadIdx.x;
    const int sg  = blockIdx.x;          // s*4 + grp
    const int s   = sg >> 2, grp = sg & 3;
    const int bb  = tid >> 4, kq = tid & 15;

    const float* src = x + ((size_t)(grp * 16 + bb) * S_LEN + s) * IDIM + kq * 16;
#pragma unroll
    for (int i = 0; i < 4; i++)
        *(float4*)(ts + bb * 260 + kq * 16 + 4 * i) = *(const float4*)(src + 4 * i);
    __syncthreads();

    float* dst = g_xT + ((size_t)sg * 256 + tid) * 16;
#pragma unroll
    for (int q = 0; q < 4; q++) {
        float4 o;
        o.x = ts[(4 * q + 0) * 260 + tid];
        o.y = ts[(4 * q + 1) * 260 + tid];
        o.z = ts[(4 * q + 2) * 260 + tid];
        o.w = ts[(4 * q + 3) * 260 + tid];
        *(float4*)(dst + 4 * q) = o;
    }
}

// =============================================================================
// Fully-fused GRU: gi + recurrence + OUTPUT PROJECTION in one persistent
// kernel. 4 groups x 32 CTAs; slice = 16 j (gates) = 16 o-cols (output).
// w_hh (96 regs) + w_out slice (32 regs) register-resident; w_ih in SMEM.
// Per step: gi_A | poll+LDG h | gi_B ; STS h; bar1; gh-FMA; dump; bar2;
// reduce+gates; STG hsT; bar_A; RELEASE; out-FMA (pos s-1, fills the
// release->peer-consume window); out dump (reuses sred); x STS; bar_B;
// out reduce; STG out.  Epilogue handles out[511].
// =============================================================================
__global__ __launch_bounds__(256, 1)
void gru_scan(const float* __restrict__ w_ih, const float* __restrict__ w_hh,
              const float* __restrict__ b_ih, const float* __restrict__ b_hh,
              const float* __restrict__ w_out, const float* __restrict__ b_out,
              float* __restrict__ out)
{
    extern __shared__ float sm[];
    float* sh_h = sm;                      // 8192  : h [k512][b16]
    float* sred = sm + 8192;               // 17408 : partials 256 x RSTR (reused for out)
    float* sx   = sm + 8192 + 17408;       // 8192  : x tiles, 2 x [k256][b16]
    float* sw   = sx + 8192;               // 12336 : w_ih slice [48][257]

    const int tid     = threadIdx.x;
    const int lane    = tid & 31;
    const int wrp     = tid >> 5;          // warp id = exchange block id
    const int grp     = blockIdx.x >> 5;
    const int slice   = blockIdx.x & 31;
    const int j0      = slice * 16;        // hidden slice AND o-col slice base
    const int b0      = grp * 16;
    const int own_blk = slice >> 2;
    const int kI      = tid >> 4;          // k-chunk id 0..15
    const int jI      = tid & 15;          // hidden unit / o-col in slice
    const int jj      = kI;                // gate/out-reduce hidden idx
    const int bbat    = jI;                // gate/out-reduce batch idx

    // ---- w_hh register-resident (k = kI + 16*m) ----------------------------
    float w[3][32];
#pragma unroll
    for (int g = 0; g < 3; g++) {
        const float* p = w_hh + (size_t)(g * HID + j0 + jI) * HID + kI;
#pragma unroll
        for (int m = 0; m < 32; m++) w[g][m] = p[16 * m];
    }
    // ---- w_out slice register-resident: col o0+jI, k = kI + 16*m -----------
    float wo[32];
    {
        const float* p = w_out + (size_t)(j0 + jI) * HID + kI;
#pragma unroll
        for (int m = 0; m < 32; m++) wo[m] = p[16 * m];
    }

    // ---- stage w_ih slice into SMEM (rows (g,j), pad 257) ------------------
    for (int i = tid; i < 48 * 256; i += 256) {
        int row = i >> 8, k = i & 255;
        int g = row >> 4, jr = row & 15;
        sw[row * 257 + k] = w_ih[(size_t)(g * HID + j0 + jr) * IDIM + k];
    }

    // ---- fused biases ------------------------------------------------------
    const float bR  = b_ih[j0 + jj]           + b_hh[j0 + jj];
    const float bZ  = b_ih[HID + j0 + jj]     + b_hh[HID + j0 + jj];
    const float bIN = b_ih[2 * HID + j0 + jj];
    const float bHN = b_hh[2 * HID + j0 + jj];
    const float bO  = b_out[j0 + jj];

    for (int i = tid; i < 8192; i += 256) sh_h[i] = 0.f;   // h_0 = 0
    {   // stage x tile for step 0
        const float4* src = (const float4*)(g_xT + (size_t)grp * 4096);
        float4* dst = (float4*)sx;
#pragma unroll
        for (int i = 0; i < 4; i++) dst[tid + 256 * i] = src[tid + 256 * i];
    }
    __syncthreads();

    for (int s = 0; s < S_LEN; s++) {
        float2 acc[8][4];
#pragma unroll
        for (int p = 0; p < 8; p++)
#pragma unroll
            for (int g = 0; g < 4; g++) acc[p][g] = make_float2(0.f, 0.f);

        const float* xrow = sx + (s & 1) * 4096 + kI * 256;
        const float* swr = sw + jI * 257        + kI * 16;
        const float* swz = sw + (16 + jI) * 257 + kI * 16;
        const float* swn = sw + (32 + jI) * 257 + kI * 16;

        // ---- gi chunk A (kk 0..7) -----------------------------------------
#pragma unroll 4
        for (int kk = 0; kk < 8; kk++) {
            float2 WR = {swr[kk], swr[kk]}, WZ = {swz[kk], swz[kk]}, WN = {swn[kk], swn[kk]};
            const float* xr = xrow + kk * 16;
#pragma unroll
            for (int q = 0; q < 4; q++) {
                float4 x4 = *(const float4*)(xr + 4 * q);
                float2 x01 = {x4.x, x4.y}, x23 = {x4.z, x4.w};
                acc[2 * q][0]     = ffma2(x01, WR, acc[2 * q][0]);
                acc[2 * q][1]     = ffma2(x01, WZ, acc[2 * q][1]);
                acc[2 * q][3]     = ffma2(x01, WN, acc[2 * q][3]);
                acc[2 * q + 1][0] = ffma2(x23, WR, acc[2 * q + 1][0]);
                acc[2 * q + 1][1] = ffma2(x23, WZ, acc[2 * q + 1][1]);
                acc[2 * q + 1][3] = ffma2(x23, WN, acc[2 * q + 1][3]);
            }
        }

        // ---- poll (fast path: data is ~a full out-phase old) + LDG h -------
        float4 h0, h1, h2, h3, h4, h5, h6, h7;
        if (s > 0) {
            if (lane == 0) poll_ge(&g_blk[(grp * 8 + wrp) * 64], 4u * (unsigned)s);
            __syncwarp();
            const float4* srcb = (const float4*)(g_hsT + ((size_t)s * 4 + grp) * 8192)
                                 + wrp * 256 + lane;
            h0 = srcb[0];   h1 = srcb[32];  h2 = srcb[64];  h3 = srcb[96];
            h4 = srcb[128]; h5 = srcb[160]; h6 = srcb[192]; h7 = srcb[224];
        }

        // ---- gi chunk B (kk 8..15) — hides h LDG latency -------------------
#pragma unroll 4
        for (int kk = 8; kk < 16; kk++) {
            float2 WR = {swr[kk], swr[kk]}, WZ = {swz[kk], swz[kk]}, WN = {swn[kk], swn[kk]};
            const float* xr = xrow + kk * 16;
#pragma unroll
            for (int q = 0; q < 4; q++) {
                float4 x4 = *(const float4*)(xr + 4 * q);
                float2 x01 = {x4.x, x4.y}, x23 = {x4.z, x4.w};
                acc[2 * q][0]     = ffma2(x01, WR, acc[2 * q][0]);
                acc[2 * q][1]     = ffma2(x01, WZ, acc[2 * q][1]);
                acc[2 * q][3]     = ffma2(x01, WN, acc[2 * q][3]);
                acc[2 * q + 1][0] = ffma2(x23, WR, acc[2 * q + 1][0]);
                acc[2 * q + 1][1] = ffma2(x23, WZ, acc[2 * q + 1][1]);
                acc[2 * q + 1][3] = ffma2(x23, WN, acc[2 * q + 1][3]);
            }
        }

        if (s > 0) {
            float4* dstb = (float4*)sh_h + wrp * 256 + lane;
            dstb[0]   = h0; dstb[32]  = h1; dstb[64]  = h2; dstb[96]  = h3;
            dstb[128] = h4; dstb[160] = h5; dstb[192] = h6; dstb[224] = h7;
        }
        __syncthreads();                                          // bar1

        // ---- gh-FMA over full 512 k (planes 0,1,2) -------------------------
        if (s > 0) {
#pragma unroll
            for (int m = 0; m < 32; m++) {
                const float* hr = sh_h + (kI + 16 * m) * 16;
                float2 WR = {w[0][m], w[0][m]};
                float2 WZ = {w[1][m], w[1][m]};
                float2 WN = {w[2][m], w[2][m]};
#pragma unroll
                for (int q = 0; q < 4; q++) {
                    float4 h4v = *(const float4*)(hr + 4 * q);
                    float2 h01 = {h4v.x, h4v.y}, h23 = {h4v.z, h4v.w};
                    acc[2 * q][0]     = ffma2(h01, WR, acc[2 * q][0]);
                    acc[2 * q][1]     = ffma2(h01, WZ, acc[2 * q][1]);
                    acc[2 * q][2]     = ffma2(h01, WN, acc[2 * q][2]);
                    acc[2 * q + 1][0] = ffma2(h23, WR, acc[2 * q + 1][0]);
                    acc[2 * q + 1][1] = ffma2(h23, WZ, acc[2 * q + 1][1]);
                    acc[2 * q + 1][2] = ffma2(h23, WN, acc[2 * q + 1][2]);
                }
            }
        }

        // ---- dump: 16 waste-free STS.128 -----------------------------------
        {
            float* rp = sred + tid * RSTR;
#pragma unroll
            for (int p = 0; p < 8; p++) {
                *(float4*)(rp + 8 * p)     =
                    make_float4(acc[p][0].x, acc[p][1].x, acc[p][2].x, acc[p][3].x);
                *(float4*)(rp + 8 * p + 4) =
                    make_float4(acc[p][0].y, acc[p][1].y, acc[p][2].y, acc[p][3].y);
            }
        }
        __syncthreads();                                          // bar2

        // ---- x prefetch for s+1 --------------------------------------------
        float4 xf0, xf1, xf2, xf3;
        if (s + 1 < S_LEN) {
            const float4* xsrc = (const float4*)(g_xT + ((size_t)(s + 1) * 4 + grp) * 4096);
            xf0 = xsrc[tid]; xf1 = xsrc[tid + 256]; xf2 = xsrc[tid + 512]; xf3 = xsrc[tid + 768];
        }

        // ---- reduce + gates + hsT store ------------------------------------
        {
            float R = bR, Z = bZ, GN = 0.f, GI = bIN;
#pragma unroll
            for (int kc = 0; kc < 16; kc++) {
                float4 v = *(const float4*)(sred + (kc * 16 + jj) * RSTR + 4 * bbat);
                R += v.x; Z += v.y; GN += v.z; GI += v.w;
            }
            float r = fast_sigmoid(R);
            float z = fast_sigmoid(Z);
            float n = fast_tanh(GI + r * (GN + bHN));
            float hp = sh_h[(j0 + jj) * 16 + bbat];
            float hn = (1.f - z) * n + z * hp;
            g_hsT[((size_t)(s + 1) * 4 + grp) * 8192 + (j0 + jj) * 16 + bbat] = hn;
        }
        __syncthreads();                                          // bar_A

        if (tid == 0) {
            unsigned* ctr = &g_blk[(grp * 8 + own_blk) * 64];
            asm volatile("red.release.gpu.global.add.u32 [%0], 1;" :: "l"(ctr) : "memory");
        }

        // ================= OUT PROJECTION for position s-1 ==================
        // (fills the release->peer-consume window; sh_h still holds hs[s-1])
        if (s > 0) {
            float2 oacc[8];
#pragma unroll
            for (int p = 0; p < 8; p++) oacc[p] = make_float2(0.f, 0.f);
#pragma unroll
            for (int m = 0; m < 32; m++) {
                const float* hr = sh_h + (kI + 16 * m) * 16;
                float2 WO = {wo[m], wo[m]};
#pragma unroll
                for (int q = 0; q < 4; q++) {
                    float4 h4v = *(const float4*)(hr + 4 * q);
                    oacc[2 * q]     = ffma2(make_float2(h4v.x, h4v.y), WO, oacc[2 * q]);
                    oacc[2 * q + 1] = ffma2(make_float2(h4v.z, h4v.w), WO, oacc[2 * q + 1]);
                }
            }
            float* rp = sred + tid * RSTR;
#pragma unroll
            for (int j = 0; j < 4; j++)
                *(float4*)(rp + 4 * j) = make_float4(oacc[2 * j].x, oacc[2 * j].y,
                                                     oacc[2 * j + 1].x, oacc[2 * j + 1].y);
        }

        if (s + 1 < S_LEN) {     // x STS before bar_B (ordered for next gi)
            float4* xd = (float4*)(sx + ((s + 1) & 1) * 4096);
            xd[tid] = xf0; xd[tid + 256] = xf1; xd[tid + 512] = xf2; xd[tid + 768] = xf3;
        }
        __syncthreads();                                          // bar_B

        if (s > 0) {             // out reduce + store (position s-1)
            float o = bO;
#pragma unroll
            for (int kc = 0; kc < 16; kc++)
                o += sred[(kc * 16 + jj) * RSTR + bbat];
            out[((size_t)(b0 + bbat) * S_LEN + (s - 1)) * ODIM + j0 + jj] = o;
        }
    }

    // ================= epilogue: out[511] ===================================
    {
        if (lane == 0) poll_ge(&g_blk[(grp * 8 + wrp) * 64], 4u * (unsigned)S_LEN);
        __syncwarp();
        const float4* srcb = (const float4*)(g_hsT + ((size_t)S_LEN * 4 + grp) * 8192)
                             + wrp * 256 + lane;
        float4 h0 = srcb[0],   h1 = srcb[32],  h2 = srcb[64],  h3 = srcb[96];
        float4 h4 = srcb[128], h5 = srcb[160], h6 = srcb[192], h7 = srcb[224];
        float4* dstb = (float4*)sh_h + wrp * 256 + lane;
        dstb[0]   = h0; dstb[32]  = h1; dstb[64]  = h2; dstb[96]  = h3;
        dstb[128] = h4; dstb[160] = h5; dstb[192] = h6; dstb[224] = h7;
        __syncthreads();

        float2 oacc[8];
#pragma unroll
        for (int p = 0; p < 8; p++) oacc[p] = make_float2(0.f, 0.f);
#pragma unroll
        for (int m = 0; m < 32; m++) {
            const float* hr = sh_h + (kI + 16 * m) * 16;
            float2 WO = {wo[m], wo[m]};
#pragma unroll
            for (int q = 0; q < 4; q++) {
                float4 h4v = *(const float4*)(hr + 4 * q);
                oacc[2 * q]     = ffma2(make_float2(h4v.x, h4v.y), WO, oacc[2 * q]);
                oacc[2 * q + 1] = ffma2(make_float2(h4v.z, h4v.w), WO, oacc[2 * q + 1]);
            }
        }
        float* rp = sred + tid * RSTR;
#pragma unroll
        for (int j = 0; j < 4; j++)
            *(float4*)(rp + 4 * j) = make_float4(oacc[2 * j].x, oacc[2 * j].y,
                                                 oacc[2 * j + 1].x, oacc[2 * j + 1].y);
        __syncthreads();

        float o = bO;
#pragma unroll
        for (int kc = 0; kc < 16; kc++)
            o += sred[(kc * 16 + jj) * RSTR + bbat];
        out[((size_t)(b0 + bbat) * S_LEN + (S_LEN - 1)) * ODIM + j0 + jj] = o;
    }
}

// =============================================================================
extern "C" void kernel_launch(void* const* d_in, const int* in_sizes, int n_in,
                              void* d_out, int out_size)
{
    (void)in_sizes; (void)n_in; (void)out_size;
    const float* x     = (const float*)d_in[0];
    const float* w_ih  = (const float*)d_in[1];
    const float* w_hh  = (const float*)d_in[2];
    const float* b_ih  = (const float*)d_in[3];
    const float* b_hh  = (const float*)d_in[4];
    const float* w_out = (const float*)d_in[5];
    const float* b_out = (const float*)d_in[6];
    float* out = (float*)d_out;

    void* p_blk = nullptr;
    cudaGetSymbolAddress(&p_blk, g_blk);
    cudaMemsetAsync(p_blk, 0, sizeof(unsigned) * 4 * 8 * 64);

    const int scan_smem = (8192 + 256 * RSTR + 8192 + 48 * 257) * 4;   // 184512 B
    cudaFuncSetAttribute(gru_scan, cudaFuncAttributeMaxDynamicSharedMemorySize, scan_smem);

    // Phase 0: transpose x into [s][grp][k][b16]
    transpose_x<<<S_LEN * 4, 256>>>(x);

    // Phase 1: fully-fused GRU (gi + scan + output projection)
    gru_scan<<<128, 256, scan_smem>>>(w_ih, w_hh, b_ih, b_hh, w_out, b_out, out);
}

// round 10
// speedup vs baseline: 1.1196x; 1.1196x over previous
#include <cuda_runtime.h>
#include <cstring>
#include <cstdint>

#define S_LEN 512
#define BATCH 64
#define IDIM  256
#define HID   512
#define ODIM  512    // 2*O

#define RSTR 68      // sred row stride in floats: 272B = 16B-aligned, conflict-free

// ---------------- scratch (static device globals; no allocation) -------------
__device__ float    g_hsT[(size_t)(S_LEN + 1) * 4 * HID * 16];  // [step][grp][k512][b16]
__device__ float    g_xT [(size_t)S_LEN * 4 * IDIM * 16];       // [s][grp][k256][b16]
__device__ unsigned g_blk[4 * 8 * 64];                          // per-(grp,block) counters

// ---------------- packed f32x2 FMA (full-rate fp32 on sm_100a) ---------------
__device__ __forceinline__ float2 ffma2(float2 a, float2 b, float2 c) {
#if defined(__CUDA_ARCH__) && (__CUDA_ARCH__ >= 1000)
    unsigned long long au, bu, cu, du;
    memcpy(&au, &a, 8); memcpy(&bu, &b, 8); memcpy(&cu, &c, 8);
    asm("fma.rn.f32x2 %0, %1, %2, %3;" : "=l"(du) : "l"(au), "l"(bu), "l"(cu));
    float2 d; memcpy(&d, &du, 8);
    return d;
#else
    return make_float2(fmaf(a.x, b.x, c.x), fmaf(a.y, b.y, c.y));
#endif
}

__device__ __forceinline__ void poll_ge(const unsigned* a, unsigned need) {
    unsigned v;
    do {
        asm volatile("ld.acquire.gpu.global.u32 %0, [%1];" : "=r"(v) : "l"(a) : "memory");
    } while (v < need);
}

__device__ __forceinline__ void cp_async16(uint32_t smem, const void* gptr) {
    asm volatile("cp.async.cg.shared.global [%0], [%1], 16;" :: "r"(smem), "l"(gptr) : "memory");
}
#define CP_COMMIT() asm volatile("cp.async.commit_group;" ::: "memory")
#define CP_WAIT0()  asm volatile("cp.async.wait_group 0;"  ::: "memory")

__device__ __forceinline__ float fast_sigmoid(float x) {
    return __fdividef(1.f, 1.f + __expf(-x));
}
__device__ __forceinline__ float fast_tanh(float x) {
    return __fdividef(2.f, 1.f + __expf(-2.f * x)) - 1.f;
}

// =============================================================================
// Prologue: x[b][s][k] -> g_xT[s][grp][k][b16]  (smem transpose, coalesced)
// =============================================================================
__global__ __launch_bounds__(256)
void transpose_x(const float* __restrict__ x)
{
    __shared__ float ts[16 * 260];
    const int tid = threadIdx.x;
    const int sg  = blockIdx.x;          // s*4 + grp
    const int s   = sg >> 2, grp = sg & 3;
    const int bb  = tid >> 4, kq = tid & 15;

    const float* src = x + ((size_t)(grp * 16 + bb) * S_LEN + s) * IDIM + kq * 16;
#pragma unroll
    for (int i = 0; i < 4; i++)
        *(float4*)(ts + bb * 260 + kq * 16 + 4 * i) = *(const float4*)(src + 4 * i);
    __syncthreads();

    float* dst = g_xT + ((size_t)sg * 256 + tid) * 16;
#pragma unroll
    for (int q = 0; q < 4; q++) {
        float4 o;
        o.x = ts[(4 * q + 0) * 260 + tid];
        o.y = ts[(4 * q + 1) * 260 + tid];
        o.z = ts[(4 * q + 2) * 260 + tid];
        o.w = ts[(4 * q + 3) * 260 + tid];
        *(float4*)(dst + 4 * q) = o;
    }
}

// =============================================================================
// Fully-fused GRU: gi + recurrence + output projection, register-safe:
// all global->shared staging via cp.async (no register staging).
// =============================================================================
__global__ __launch_bounds__(256, 1)
void gru_scan(const float* __restrict__ w_ih, const float* __restrict__ w_hh,
              const float* __restrict__ b_ih, const float* __restrict__ b_hh,
              const float* __restrict__ w_out, const float* __restrict__ b_out,
              float* __restrict__ out)
{
    extern __shared__ float sm[];
    float* sh_h = sm;                      // 8192  : h [k512][b16]
    float* sred = sm + 8192;               // 17408 : partials 256 x RSTR (reused for out)
    float* sx   = sm + 8192 + 17408;       // 8192  : x tiles, 2 x [k256][b16]
    float* sw   = sx + 8192;               // 12336 : w_ih slice [48][257]

    const uint32_t sh_h_u = (uint32_t)__cvta_generic_to_shared(sh_h);
    const uint32_t sx_u   = (uint32_t)__cvta_generic_to_shared(sx);

    const int tid     = threadIdx.x;
    const int lane    = tid & 31;
    const int wrp     = tid >> 5;          // warp id = exchange block id
    const int grp     = blockIdx.x >> 5;
    const int slice   = blockIdx.x & 31;
    const int j0      = slice * 16;        // hidden slice AND o-col slice base
    const int b0      = grp * 16;
    const int own_blk = slice >> 2;
    const int kI      = tid >> 4;          // k-chunk id 0..15
    const int jI      = tid & 15;          // hidden unit / o-col in slice
    const int jj      = kI;                // gate/out-reduce hidden idx
    const int bbat    = jI;                // gate/out-reduce batch idx

    // ---- w_hh register-resident (k = kI + 16*m) ----------------------------
    float w[3][32];
#pragma unroll
    for (int g = 0; g < 3; g++) {
        const float* p = w_hh + (size_t)(g * HID + j0 + jI) * HID + kI;
#pragma unroll
        for (int m = 0; m < 32; m++) w[g][m] = p[16 * m];
    }
    // ---- w_out slice register-resident: col j0+jI, k = kI + 16*m -----------
    float wo[32];
    {
        const float* p = w_out + (size_t)(j0 + jI) * HID + kI;
#pragma unroll
        for (int m = 0; m < 32; m++) wo[m] = p[16 * m];
    }

    // ---- stage w_ih slice into SMEM (rows (g,j), pad 257) ------------------
    for (int i = tid; i < 48 * 256; i += 256) {
        int row = i >> 8, k = i & 255;
        int g = row >> 4, jr = row & 15;
        sw[row * 257 + k] = w_ih[(size_t)(g * HID + j0 + jr) * IDIM + k];
    }

    // ---- fused biases ------------------------------------------------------
    const float bR  = b_ih[j0 + jj]           + b_hh[j0 + jj];
    const float bZ  = b_ih[HID + j0 + jj]     + b_hh[HID + j0 + jj];
    const float bIN = b_ih[2 * HID + j0 + jj];
    const float bHN = b_hh[2 * HID + j0 + jj];
    const float bO  = b_out[j0 + jj];

    for (int i = tid; i < 8192; i += 256) sh_h[i] = 0.f;   // h_0 = 0
    {   // stage x tile for step 0
        const float4* src = (const float4*)(g_xT + (size_t)grp * 4096);
        float4* dst = (float4*)sx;
#pragma unroll
        for (int i = 0; i < 4; i++) dst[tid + 256 * i] = src[tid + 256 * i];
    }
    __syncthreads();

    for (int s = 0; s < S_LEN; s++) {
        float2 acc[8][4];
#pragma unroll
        for (int p = 0; p < 8; p++)
#pragma unroll
            for (int g = 0; g < 4; g++) acc[p][g] = make_float2(0.f, 0.f);

        const float* xrow = sx + (s & 1) * 4096 + kI * 256;
        const float* swr = sw + jI * 257        + kI * 16;
        const float* swz = sw + (16 + jI) * 257 + kI * 16;
        const float* swn = sw + (32 + jI) * 257 + kI * 16;

        // ---- gi chunk A (kk 0..7) -----------------------------------------
#pragma unroll 4
        for (int kk = 0; kk < 8; kk++) {
            float2 WR = {swr[kk], swr[kk]}, WZ = {swz[kk], swz[kk]}, WN = {swn[kk], swn[kk]};
            const float* xr = xrow + kk * 16;
#pragma unroll
            for (int q = 0; q < 4; q++) {
                float4 x4 = *(const float4*)(xr + 4 * q);
                float2 x01 = {x4.x, x4.y}, x23 = {x4.z, x4.w};
                acc[2 * q][0]     = ffma2(x01, WR, acc[2 * q][0]);
                acc[2 * q][1]     = ffma2(x01, WZ, acc[2 * q][1]);
                acc[2 * q][3]     = ffma2(x01, WN, acc[2 * q][3]);
                acc[2 * q + 1][0] = ffma2(x23, WR, acc[2 * q + 1][0]);
                acc[2 * q + 1][1] = ffma2(x23, WZ, acc[2 * q + 1][1]);
                acc[2 * q + 1][3] = ffma2(x23, WN, acc[2 * q + 1][3]);
            }
        }

        // ---- poll + cp.async h block (no register staging) -----------------
        if (s > 0) {
            if (lane == 0) poll_ge(&g_blk[(grp * 8 + wrp) * 64], 4u * (unsigned)s);
            __syncwarp();
            const float4* srcb = (const float4*)(g_hsT + ((size_t)s * 4 + grp) * 8192)
                                 + wrp * 256 + lane;
            uint32_t d = sh_h_u + (uint32_t)(wrp * 256 + lane) * 16;
#pragma unroll
            for (int i = 0; i < 8; i++)
                cp_async16(d + (uint32_t)i * 32 * 16, srcb + 32 * i);
            CP_COMMIT();
        }

        // ---- gi chunk B (kk 8..15) — hides cp.async latency ----------------
#pragma unroll 4
        for (int kk = 8; kk < 16; kk++) {
            float2 WR = {swr[kk], swr[kk]}, WZ = {swz[kk], swz[kk]}, WN = {swn[kk], swn[kk]};
            const float* xr = xrow + kk * 16;
#pragma unroll
            for (int q = 0; q < 4; q++) {
                float4 x4 = *(const float4*)(xr + 4 * q);
                float2 x01 = {x4.x, x4.y}, x23 = {x4.z, x4.w};
                acc[2 * q][0]     = ffma2(x01, WR, acc[2 * q][0]);
                acc[2 * q][1]     = ffma2(x01, WZ, acc[2 * q][1]);
                acc[2 * q][3]     = ffma2(x01, WN, acc[2 * q][3]);
                acc[2 * q + 1][0] = ffma2(x23, WR, acc[2 * q + 1][0]);
                acc[2 * q + 1][1] = ffma2(x23, WZ, acc[2 * q + 1][1]);
                acc[2 * q + 1][3] = ffma2(x23, WN, acc[2 * q + 1][3]);
            }
        }

        if (s > 0) CP_WAIT0();
        __syncthreads();                                          // bar1

        // ---- gh-FMA over full 512 k (planes 0,1,2) -------------------------
        if (s > 0) {
#pragma unroll
            for (int m = 0; m < 32; m++) {
                const float* hr = sh_h + (kI + 16 * m) * 16;
                float2 WR = {w[0][m], w[0][m]};
                float2 WZ = {w[1][m], w[1][m]};
                float2 WN = {w[2][m], w[2][m]};
#pragma unroll
                for (int q = 0; q < 4; q++) {
                    float4 h4v = *(const float4*)(hr + 4 * q);
                    float2 h01 = {h4v.x, h4v.y}, h23 = {h4v.z, h4v.w};
                    acc[2 * q][0]     = ffma2(h01, WR, acc[2 * q][0]);
                    acc[2 * q][1]     = ffma2(h01, WZ, acc[2 * q][1]);
                    acc[2 * q][2]     = ffma2(h01, WN, acc[2 * q][2]);
                    acc[2 * q + 1][0] = ffma2(h23, WR, acc[2 * q + 1][0]);
                    acc[2 * q + 1][1] = ffma2(h23, WZ, acc[2 * q + 1][1]);
                    acc[2 * q + 1][2] = ffma2(h23, WN, acc[2 * q + 1][2]);
                }
            }
        }

        // ---- dump: 16 waste-free STS.128 -----------------------------------
        {
            float* rp = sred + tid * RSTR;
#pragma unroll
            for (int p = 0; p < 8; p++) {
                *(float4*)(rp + 8 * p)     =
                    make_float4(acc[p][0].x, acc[p][1].x, acc[p][2].x, acc[p][3].x);
                *(float4*)(rp + 8 * p + 4) =
                    make_float4(acc[p][0].y, acc[p][1].y, acc[p][2].y, acc[p][3].y);
            }
        }
        __syncthreads();                                          // bar2

        // ---- x(s+1) prefetch straight to SMEM via cp.async -----------------
        if (s + 1 < S_LEN) {
            const float4* xsrc = (const float4*)(g_xT + ((size_t)(s + 1) * 4 + grp) * 4096);
            uint32_t d = sx_u + (uint32_t)(((s + 1) & 1) * 4096 + tid * 4) * 4;
#pragma unroll
            for (int i = 0; i < 4; i++)
                cp_async16(d + (uint32_t)i * 256 * 16, xsrc + tid + 256 * i);
            CP_COMMIT();
        }

        // ---- reduce + gates + hsT store ------------------------------------
        {
            float R = bR, Z = bZ, GN = 0.f, GI = bIN;
#pragma unroll
            for (int kc = 0; kc < 16; kc++) {
                float4 v = *(const float4*)(sred + (kc * 16 + jj) * RSTR + 4 * bbat);
                R += v.x; Z += v.y; GN += v.z; GI += v.w;
            }
            float r = fast_sigmoid(R);
            float z = fast_sigmoid(Z);
            float n = fast_tanh(GI + r * (GN + bHN));
            float hp = sh_h[(j0 + jj) * 16 + bbat];
            float hn = (1.f - z) * n + z * hp;
            g_hsT[((size_t)(s + 1) * 4 + grp) * 8192 + (j0 + jj) * 16 + bbat] = hn;
        }
        __syncthreads();                                          // bar_A

        if (tid == 0) {
            unsigned* ctr = &g_blk[(grp * 8 + own_blk) * 64];
            asm volatile("red.release.gpu.global.add.u32 [%0], 1;" :: "l"(ctr) : "memory");
        }

        // ================= OUT PROJECTION for position s-1 ==================
        if (s > 0) {
            float2 oacc[8];
#pragma unroll
            for (int p = 0; p < 8; p++) oacc[p] = make_float2(0.f, 0.f);
#pragma unroll
            for (int m = 0; m < 32; m++) {
                const float* hr = sh_h + (kI + 16 * m) * 16;
                float2 WO = {wo[m], wo[m]};
#pragma unroll
                for (int q = 0; q < 4; q++) {
                    float4 h4v = *(const float4*)(hr + 4 * q);
                    oacc[2 * q]     = ffma2(make_float2(h4v.x, h4v.y), WO, oacc[2 * q]);
                    oacc[2 * q + 1] = ffma2(make_float2(h4v.z, h4v.w), WO, oacc[2 * q + 1]);
                }
            }
            float* rp = sred + tid * RSTR;
#pragma unroll
            for (int j = 0; j < 4; j++)
                *(float4*)(rp + 4 * j) = make_float4(oacc[2 * j].x, oacc[2 * j].y,
                                                     oacc[2 * j + 1].x, oacc[2 * j + 1].y);
        }

        if (s + 1 < S_LEN) CP_WAIT0();   // x tile landed
        __syncthreads();                                          // bar_B

        if (s > 0) {             // out reduce + store (position s-1)
            float o = bO;
#pragma unroll
            for (int kc = 0; kc < 16; kc++)
                o += sred[(kc * 16 + jj) * RSTR + bbat];
            out[((size_t)(b0 + bbat) * S_LEN + (s - 1)) * ODIM + j0 + jj] = o;
        }
    }

    // ================= epilogue: out[511] ===================================
    {
        if (lane == 0) poll_ge(&g_blk[(grp * 8 + wrp) * 64], 4u * (unsigned)S_LEN);
        __syncwarp();
        const float4* srcb = (const float4*)(g_hsT + ((size_t)S_LEN * 4 + grp) * 8192)
                             + wrp * 256 + lane;
        uint32_t d = sh_h_u + (uint32_t)(wrp * 256 + lane) * 16;
#pragma unroll
        for (int i = 0; i < 8; i++)
            cp_async16(d + (uint32_t)i * 32 * 16, srcb + 32 * i);
        CP_COMMIT();
        CP_WAIT0();
        __syncthreads();

        float2 oacc[8];
#pragma unroll
        for (int p = 0; p < 8; p++) oacc[p] = make_float2(0.f, 0.f);
#pragma unroll
        for (int m = 0; m < 32; m++) {
            const float* hr = sh_h + (kI + 16 * m) * 16;
            float2 WO = {wo[m], wo[m]};
#pragma unroll
            for (int q = 0; q < 4; q++) {
                float4 h4v = *(const float4*)(hr + 4 * q);
                oacc[2 * q]     = ffma2(make_float2(h4v.x, h4v.y), WO, oacc[2 * q]);
                oacc[2 * q + 1] = ffma2(make_float2(h4v.z, h4v.w), WO, oacc[2 * q + 1]);
            }
        }
        float* rp = sred + tid * RSTR;
#pragma unroll
        for (int j = 0; j < 4; j++)
            *(float4*)(rp + 4 * j) = make_float4(oacc[2 * j].x, oacc[2 * j].y,
                                                 oacc[2 * j + 1].x, oacc[2 * j + 1].y);
        __syncthreads();

        float o = bO;
#pragma unroll
        for (int kc = 0; kc < 16; kc++)
            o += sred[(kc * 16 + jj) * RSTR + bbat];
        out[((size_t)(b0 + bbat) * S_LEN + (S_LEN - 1)) * ODIM + j0 + jj] = o;
    }
}

// =============================================================================
extern "C" void kernel_launch(void* const* d_in, const int* in_sizes, int n_in,
                              void* d_out, int out_size)
{
    (void)in_sizes; (void)n_in; (void)out_size;
    const float* x     = (const float*)d_in[0];
    const float* w_ih  = (const float*)d_in[1];
    const float* w_hh  = (const float*)d_in[2];
    const float* b_ih  = (const float*)d_in[3];
    const float* b_hh  = (const float*)d_in[4];
    const float* w_out = (const float*)d_in[5];
    const float* b_out = (const float*)d_in[6];
    float* out = (float*)d_out;

    void* p_blk = nullptr;
    cudaGetSymbolAddress(&p_blk, g_blk);
    cudaMemsetAsync(p_blk, 0, sizeof(unsigned) * 4 * 8 * 64);

    const int scan_smem = (8192 + 256 * RSTR + 8192 + 48 * 257) * 4;   // 184512 B
    cudaFuncSetAttribute(gru_scan, cudaFuncAttributeMaxDynamicSharedMemorySize, scan_smem);

    // Phase 0: transpose x into [s][grp][k][b16]
    transpose_x<<<S_LEN * 4, 256>>>(x);

    // Phase 1: fully-fused GRU (gi + scan + output projection)
    gru_scan<<<128, 256, scan_smem>>>(w_ih, w_hh, b_ih, b_hh, w_out, b_out, out);
}

// round 12
// speedup vs baseline: 1.1265x; 1.0062x over previous
#include <cuda_runtime.h>
#include <cstring>
#include <cstdint>

#define S_LEN 512
#define BATCH 64
#define IDIM  256
#define HID   512
#define ODIM  512    // 2*O

#define RSTR 68      // sred row stride in floats: 272B = 16B-aligned, conflict-free

// ---------------- scratch (static device globals; no allocation) -------------
__device__ float    g_hsT[(size_t)(S_LEN + 1) * 4 * HID * 16];  // [step][grp][k512][b16]
__device__ float    g_xT [(size_t)S_LEN * 4 * IDIM * 16];       // [s][grp][k256][b16]
__device__ unsigned g_blk[4 * 8 * 64];                          // per-(grp,block) counters

// ---------------- packed f32x2 FMA (full-rate fp32 on sm_100a) ---------------
__device__ __forceinline__ float2 ffma2(float2 a, float2 b, float2 c) {
#if defined(__CUDA_ARCH__) && (__CUDA_ARCH__ >= 1000)
    unsigned long long au, bu, cu, du;
    memcpy(&au, &a, 8); memcpy(&bu, &b, 8); memcpy(&cu, &c, 8);
    asm("fma.rn.f32x2 %0, %1, %2, %3;" : "=l"(du) : "l"(au), "l"(bu), "l"(cu));
    float2 d; memcpy(&d, &du, 8);
    return d;
#else
    return make_float2(fmaf(a.x, b.x, c.x), fmaf(a.y, b.y, c.y));
#endif
}

__device__ __forceinline__ void poll_ge(const unsigned* a, unsigned need) {
    unsigned v;
    do {
        asm volatile("ld.acquire.gpu.global.u32 %0, [%1];" : "=r"(v) : "l"(a) : "memory");
    } while (v < need);
}

__device__ __forceinline__ void cp_async16(uint32_t smem, const void* gptr) {
    asm volatile("cp.async.cg.shared.global [%0], [%1], 16;" :: "r"(smem), "l"(gptr) : "memory");
}
#define CP_COMMIT() asm volatile("cp.async.commit_group;" ::: "memory")
#define CP_WAIT0()  asm volatile("cp.async.wait_group 0;"  ::: "memory")

__device__ __forceinline__ float fast_sigmoid(float x) {
    return __fdividef(1.f, 1.f + __expf(-x));
}
__device__ __forceinline__ float fast_tanh(float x) {
    return __fdividef(2.f, 1.f + __expf(-2.f * x)) - 1.f;
}

// =============================================================================
// Prologue: x[b][s][k] -> g_xT[s][grp][k][b16]  (smem transpose, coalesced)
// =============================================================================
__global__ __launch_bounds__(256)
void transpose_x(const float* __restrict__ x)
{
    __shared__ float ts[16 * 260];
    const int tid = threadIdx.x;
    const int sg  = blockIdx.x;          // s*4 + grp
    const int s   = sg >> 2, grp = sg & 3;
    const int bb  = tid >> 4, kq = tid & 15;

    const float* src = x + ((size_t)(grp * 16 + bb) * S_LEN + s) * IDIM + kq * 16;
#pragma unroll
    for (int i = 0; i < 4; i++)
        *(float4*)(ts + bb * 260 + kq * 16 + 4 * i) = *(const float4*)(src + 4 * i);
    __syncthreads();

    float* dst = g_xT + ((size_t)sg * 256 + tid) * 16;
#pragma unroll
    for (int q = 0; q < 4; q++) {
        float4 o;
        o.x = ts[(4 * q + 0) * 260 + tid];
        o.y = ts[(4 * q + 1) * 260 + tid];
        o.z = ts[(4 * q + 2) * 260 + tid];
        o.w = ts[(4 * q + 3) * 260 + tid];
        *(float4*)(dst + 4 * q) = o;
    }
}

// =============================================================================
// Fully-fused GRU: gi + recurrence + output projection. Register-safe:
// staging via cp.async; w_out in SMEM (swo[k][j16]) instead of registers.
// =============================================================================
__global__ __launch_bounds__(256, 1)
void gru_scan(const float* __restrict__ w_ih, const float* __restrict__ w_hh,
              const float* __restrict__ b_ih, const float* __restrict__ b_hh,
              const float* __restrict__ w_out, const float* __restrict__ b_out,
              float* __restrict__ out)
{
    extern __shared__ float sm[];
    float* sh_h = sm;                      // 8192 f : h [k512][b16]
    float* sred = sm + 8192;               // 17408 f: partials 256 x RSTR (reused for out)
    float* sx   = sm + 8192 + 17408;       // 8192 f : x tiles, 2 x [k256][b16]
    float* sw   = sx + 8192;               // 12336 f: w_ih slice [48][257]
    float* swo  = sw + 12336;              // 8192 f : w_out slice [k512][j16]

    const uint32_t sh_h_u = (uint32_t)__cvta_generic_to_shared(sh_h);
    const uint32_t sx_u   = (uint32_t)__cvta_generic_to_shared(sx);

    const int tid     = threadIdx.x;
    const int lane    = tid & 31;
    const int wrp     = tid >> 5;          // warp id = exchange block id
    const int grp     = blockIdx.x >> 5;
    const int slice   = blockIdx.x & 31;
    const int j0      = slice * 16;        // hidden slice AND o-col slice base
    const int b0      = grp * 16;
    const int own_blk = slice >> 2;
    const int kI      = tid >> 4;          // k-chunk id 0..15
    const int jI      = tid & 15;          // hidden unit / o-col in slice
    const int jj      = kI;                // gate/out-reduce hidden idx
    const int bbat    = jI;                // gate/out-reduce batch idx

    // ---- w_hh register-resident (k = kI + 16*m) ----------------------------
    float w[3][32];
#pragma unroll
    for (int g = 0; g < 3; g++) {
        const float* p = w_hh + (size_t)(g * HID + j0 + jI) * HID + kI;
#pragma unroll
        for (int m = 0; m < 32; m++) w[g][m] = p[16 * m];
    }

    // ---- stage w_ih slice into SMEM (rows (g,j), pad 257) ------------------
    for (int i = tid; i < 48 * 256; i += 256) {
        int row = i >> 8, k = i & 255;
        int g = row >> 4, jr = row & 15;
        sw[row * 257 + k] = w_ih[(size_t)(g * HID + j0 + jr) * IDIM + k];
    }
    // ---- stage w_out slice into SMEM: swo[k*16 + j] ------------------------
    for (int i = tid; i < 512 * 16; i += 256) {
        int k = i >> 4, j = i & 15;
        swo[i] = w_out[(size_t)(j0 + j) * HID + k];
    }

    // ---- fused biases ------------------------------------------------------
    const float bR  = b_ih[j0 + jj]           + b_hh[j0 + jj];
    const float bZ  = b_ih[HID + j0 + jj]     + b_hh[HID + j0 + jj];
    const float bIN = b_ih[2 * HID + j0 + jj];
    const float bHN = b_hh[2 * HID + j0 + jj];
    const float bO  = b_out[j0 + jj];

    for (int i = tid; i < 8192; i += 256) sh_h[i] = 0.f;   // h_0 = 0
    {   // stage x tile for step 0
        const float4* src = (const float4*)(g_xT + (size_t)grp * 4096);
        float4* dst = (float4*)sx;
#pragma unroll
        for (int i = 0; i < 4; i++) dst[tid + 256 * i] = src[tid + 256 * i];
    }
    __syncthreads();

    for (int s = 0; s < S_LEN; s++) {
        float2 acc[8][4];
#pragma unroll
        for (int p = 0; p < 8; p++)
#pragma unroll
            for (int g = 0; g < 4; g++) acc[p][g] = make_float2(0.f, 0.f);

        const float* xrow = sx + (s & 1) * 4096 + kI * 256;
        const float* swr = sw + jI * 257        + kI * 16;
        const float* swz = sw + (16 + jI) * 257 + kI * 16;
        const float* swn = sw + (32 + jI) * 257 + kI * 16;

        // ---- gi chunk A (kk 0..7) -----------------------------------------
#pragma unroll 4
        for (int kk = 0; kk < 8; kk++) {
            float2 WR = {swr[kk], swr[kk]}, WZ = {swz[kk], swz[kk]}, WN = {swn[kk], swn[kk]};
            const float* xr = xrow + kk * 16;
#pragma unroll
            for (int q = 0; q < 4; q++) {
                float4 x4 = *(const float4*)(xr + 4 * q);
                float2 x01 = {x4.x, x4.y}, x23 = {x4.z, x4.w};
                acc[2 * q][0]     = ffma2(x01, WR, acc[2 * q][0]);
                acc[2 * q][1]     = ffma2(x01, WZ, acc[2 * q][1]);
                acc[2 * q][3]     = ffma2(x01, WN, acc[2 * q][3]);
                acc[2 * q + 1][0] = ffma2(x23, WR, acc[2 * q + 1][0]);
                acc[2 * q + 1][1] = ffma2(x23, WZ, acc[2 * q + 1][1]);
                acc[2 * q + 1][3] = ffma2(x23, WN, acc[2 * q + 1][3]);
            }
        }

        // ---- poll + cp.async h block (no register staging) -----------------
        if (s > 0) {
            if (lane == 0) poll_ge(&g_blk[(grp * 8 + wrp) * 64], 4u * (unsigned)s);
            __syncwarp();
            const float4* srcb = (const float4*)(g_hsT + ((size_t)s * 4 + grp) * 8192)
                                 + wrp * 256 + lane;
            uint32_t d = sh_h_u + (uint32_t)(wrp * 256 + lane) * 16;
#pragma unroll
            for (int i = 0; i < 8; i++)
                cp_async16(d + (uint32_t)i * 32 * 16, srcb + 32 * i);
            CP_COMMIT();
        }

        // ---- gi chunk B (kk 8..15) — hides cp.async latency ----------------
#pragma unroll 4
        for (int kk = 8; kk < 16; kk++) {
            float2 WR = {swr[kk], swr[kk]}, WZ = {swz[kk], swz[kk]}, WN = {swn[kk], swn[kk]};
            const float* xr = xrow + kk * 16;
#pragma unroll
            for (int q = 0; q < 4; q++) {
                float4 x4 = *(const float4*)(xr + 4 * q);
                float2 x01 = {x4.x, x4.y}, x23 = {x4.z, x4.w};
                acc[2 * q][0]     = ffma2(x01, WR, acc[2 * q][0]);
                acc[2 * q][1]     = ffma2(x01, WZ, acc[2 * q][1]);
                acc[2 * q][3]     = ffma2(x01, WN, acc[2 * q][3]);
                acc[2 * q + 1][0] = ffma2(x23, WR, acc[2 * q + 1][0]);
                acc[2 * q + 1][1] = ffma2(x23, WZ, acc[2 * q + 1][1]);
                acc[2 * q + 1][3] = ffma2(x23, WN, acc[2 * q + 1][3]);
            }
        }

        if (s > 0) CP_WAIT0();
        __syncthreads();                                          // bar1

        // ---- gh-FMA over full 512 k (planes 0,1,2) -------------------------
        if (s > 0) {
#pragma unroll
            for (int m = 0; m < 32; m++) {
                const float* hr = sh_h + (kI + 16 * m) * 16;
                float2 WR = {w[0][m], w[0][m]};
                float2 WZ = {w[1][m], w[1][m]};
                float2 WN = {w[2][m], w[2][m]};
#pragma unroll
                for (int q = 0; q < 4; q++) {
                    float4 h4v = *(const float4*)(hr + 4 * q);
                    float2 h01 = {h4v.x, h4v.y}, h23 = {h4v.z, h4v.w};
                    acc[2 * q][0]     = ffma2(h01, WR, acc[2 * q][0]);
                    acc[2 * q][1]     = ffma2(h01, WZ, acc[2 * q][1]);
                    acc[2 * q][2]     = ffma2(h01, WN, acc[2 * q][2]);
                    acc[2 * q + 1][0] = ffma2(h23, WR, acc[2 * q + 1][0]);
                    acc[2 * q + 1][1] = ffma2(h23, WZ, acc[2 * q + 1][1]);
                    acc[2 * q + 1][2] = ffma2(h23, WN, acc[2 * q + 1][2]);
                }
            }
        }

        // ---- dump: 16 waste-free STS.128 -----------------------------------
        {
            float* rp = sred + tid * RSTR;
#pragma unroll
            for (int p = 0; p < 8; p++) {
                *(float4*)(rp + 8 * p)     =
                    make_float4(acc[p][0].x, acc[p][1].x, acc[p][2].x, acc[p][3].x);
                *(float4*)(rp + 8 * p + 4) =
                    make_float4(acc[p][0].y, acc[p][1].y, acc[p][2].y, acc[p][3].y);
            }
        }
        __syncthreads();                                          // bar2

        // ---- x(s+1) prefetch straight to SMEM via cp.async -----------------
        if (s + 1 < S_LEN) {
            const float4* xsrc = (const float4*)(g_xT + ((size_t)(s + 1) * 4 + grp) * 4096);
            uint32_t d = sx_u + (uint32_t)(((s + 1) & 1) * 4096 + tid * 4) * 4;
#pragma unroll
            for (int i = 0; i < 4; i++)
                cp_async16(d + (uint32_t)i * 256 * 16, xsrc + tid + 256 * i);
            CP_COMMIT();
        }

        // ---- reduce + gates + hsT store ------------------------------------
        {
            float R = bR, Z = bZ, GN = 0.f, GI = bIN;
#pragma unroll
            for (int kc = 0; kc < 16; kc++) {
                float4 v = *(const float4*)(sred + (kc * 16 + jj) * RSTR + 4 * bbat);
                R += v.x; Z += v.y; GN += v.z; GI += v.w;
            }
            float r = fast_sigmoid(R);
            float z = fast_sigmoid(Z);
            float n = fast_tanh(GI + r * (GN + bHN));
            float hp = sh_h[(j0 + jj) * 16 + bbat];
            float hn = (1.f - z) * n + z * hp;
            g_hsT[((size_t)(s + 1) * 4 + grp) * 8192 + (j0 + jj) * 16 + bbat] = hn;
        }
        __syncthreads();                                          // bar_A

        if (tid == 0) {
            unsigned* ctr = &g_blk[(grp * 8 + own_blk) * 64];
            asm volatile("red.release.gpu.global.add.u32 [%0], 1;" :: "l"(ctr) : "memory");
        }

        // ================= OUT PROJECTION for position s-1 ==================
        // (w_out read from SMEM; fills the release->peer-consume window)
        if (s > 0) {
            float2 oacc[8];
#pragma unroll
            for (int p = 0; p < 8; p++) oacc[p] = make_float2(0.f, 0.f);
#pragma unroll
            for (int m = 0; m < 32; m++) {
                const float* hr = sh_h + (kI + 16 * m) * 16;
                float wv = swo[(kI + 16 * m) * 16 + jI];
                float2 WO = {wv, wv};
#pragma unroll
                for (int q = 0; q < 4; q++) {
                    float4 h4v = *(const float4*)(hr + 4 * q);
                    oacc[2 * q]     = ffma2(make_float2(h4v.x, h4v.y), WO, oacc[2 * q]);
                    oacc[2 * q + 1] = ffma2(make_float2(h4v.z, h4v.w), WO, oacc[2 * q + 1]);
                }
            }
            float* rp = sred + tid * RSTR;
#pragma unroll
            for (int j = 0; j < 4; j++)
                *(float4*)(rp + 4 * j) = make_float4(oacc[2 * j].x, oacc[2 * j].y,
                                                     oacc[2 * j + 1].x, oacc[2 * j + 1].y);
        }

        if (s + 1 < S_LEN) CP_WAIT0();   // x tile landed
        __syncthreads();                                          // bar_B

        if (s > 0) {             // out reduce + store (position s-1)
            float o = bO;
#pragma unroll
            for (int kc = 0; kc < 16; kc++)
                o += sred[(kc * 16 + jj) * RSTR + bbat];
            out[((size_t)(b0 + bbat) * S_LEN + (s - 1)) * ODIM + j0 + jj] = o;
        }
    }

    // ================= epilogue: out[511] ===================================
    {
        if (lane == 0) poll_ge(&g_blk[(grp * 8 + wrp) * 64], 4u * (unsigned)S_LEN);
        __syncwarp();
        const float4* srcb = (const float4*)(g_hsT + ((size_t)S_LEN * 4 + grp) * 8192)
                             + wrp * 256 + lane;
        uint32_t d = sh_h_u + (uint32_t)(wrp * 256 + lane) * 16;
#pragma unroll
        for (int i = 0; i < 8; i++)
            cp_async16(d + (uint32_t)i * 32 * 16, srcb + 32 * i);
        CP_COMMIT();
        CP_WAIT0();
        __syncthreads();

        float2 oacc[8];
#pragma unroll
        for (int p = 0; p < 8; p++) oacc[p] = make_float2(0.f, 0.f);
#pragma unroll
        for (int m = 0; m < 32; m++) {
            const float* hr = sh_h + (kI + 16 * m) * 16;
            float wv = swo[(kI + 16 * m) * 16 + jI];
            float2 WO = {wv, wv};
#pragma unroll
            for (int q = 0; q < 4; q++) {
                float4 h4v = *(const float4*)(hr + 4 * q);
                oacc[2 * q]     = ffma2(make_float2(h4v.x, h4v.y), WO, oacc[2 * q]);
                oacc[2 * q + 1] = ffma2(make_float2(h4v.z, h4v.w), WO, oacc[2 * q + 1]);
            }
        }
        float* rp = sred + tid * RSTR;
#pragma unroll
        for (int j = 0; j < 4; j++)
            *(float4*)(rp + 4 * j) = make_float4(oacc[2 * j].x, oacc[2 * j].y,
                                                 oacc[2 * j + 1].x, oacc[2 * j + 1].y);
        __syncthreads();

        float o = bO;
#pragma unroll
        for (int kc = 0; kc < 16; kc++)
            o += sred[(kc * 16 + jj) * RSTR + bbat];
        out[((size_t)(b0 + bbat) * S_LEN + (S_LEN - 1)) * ODIM + j0 + jj] = o;
    }
}

// =============================================================================
extern "C" void kernel_launch(void* const* d_in, const int* in_sizes, int n_in,
                              void* d_out, int out_size)
{
    (void)in_sizes; (void)n_in; (void)out_size;
    const float* x     = (const float*)d_in[0];
    const float* w_ih  = (const float*)d_in[1];
    const float* w_hh  = (const float*)d_in[2];
    const float* b_ih  = (const float*)d_in[3];
    const float* b_hh  = (const float*)d_in[4];
    const float* w_out = (const float*)d_in[5];
    const float* b_out = (const float*)d_in[6];
    float* out = (float*)d_out;

    void* p_blk = nullptr;
    cudaGetSymbolAddress(&p_blk, g_blk);
    cudaMemsetAsync(p_blk, 0, sizeof(unsigned) * 4 * 8 * 64);

    const int scan_smem = (8192 + 256 * RSTR + 8192 + 48 * 257 + 8192) * 4;  // 217280 B
    cudaFuncSetAttribute(gru_scan, cudaFuncAttributeMaxDynamicSharedMemorySize, scan_smem);

    // Phase 0: transpose x into [s][grp][k][b16]
    transpose_x<<<S_LEN * 4, 256>>>(x);

    // Phase 1: fully-fused GRU (gi + scan + output projection)
    gru_scan<<<128, 256, scan_smem>>>(w_ih, w_hh, b_ih, b_hh, w_out, b_out, out);
}

// round 13
// speedup vs baseline: 1.2678x; 1.1254x over previous
#include <cuda_runtime.h>
#include <cstring>
#include <cstdint>

#define S_LEN 512
#define BATCH 64
#define IDIM  256
#define HID   512
#define ODIM  512    // 2*O

#define RSTR 68      // sred row stride in floats: 272B = 16B-aligned, conflict-free

// ---------------- scratch (static device globals; no allocation) -------------
__device__ float    g_hs [(size_t)S_LEN * BATCH * HID];         // [S][B][H] -> GEMM2
__device__ float    g_hsT[(size_t)(S_LEN + 1) * 4 * HID * 16];  // [step][grp][k512][b16]
__device__ float    g_xT [(size_t)S_LEN * 4 * IDIM * 16];       // [s][grp][k256][b16]
__device__ unsigned g_blk[4 * 8 * 64];                          // per-(grp,block) counters

// ---------------- packed f32x2 FMA (full-rate fp32 on sm_100a) ---------------
__device__ __forceinline__ float2 ffma2(float2 a, float2 b, float2 c) {
#if defined(__CUDA_ARCH__) && (__CUDA_ARCH__ >= 1000)
    unsigned long long au, bu, cu, du;
    memcpy(&au, &a, 8); memcpy(&bu, &b, 8); memcpy(&cu, &c, 8);
    asm("fma.rn.f32x2 %0, %1, %2, %3;" : "=l"(du) : "l"(au), "l"(bu), "l"(cu));
    float2 d; memcpy(&d, &du, 8);
    return d;
#else
    return make_float2(fmaf(a.x, b.x, c.x), fmaf(a.y, b.y, c.y));
#endif
}

__device__ __forceinline__ void poll_ge(const unsigned* a, unsigned need) {
    unsigned v;
    do {
        asm volatile("ld.acquire.gpu.global.u32 %0, [%1];" : "=r"(v) : "l"(a) : "memory");
    } while (v < need);
}

__device__ __forceinline__ void cp_async16(uint32_t smem, const void* gptr) {
    asm volatile("cp.async.cg.shared.global [%0], [%1], 16;" :: "r"(smem), "l"(gptr) : "memory");
}
#define CP_COMMIT() asm volatile("cp.async.commit_group;" ::: "memory")
#define CP_WAIT0()  asm volatile("cp.async.wait_group 0;"  ::: "memory")

__device__ __forceinline__ float fast_sigmoid(float x) {
    return __fdividef(1.f, 1.f + __expf(-x));
}
__device__ __forceinline__ float fast_tanh(float x) {
    return __fdividef(2.f, 1.f + __expf(-2.f * x)) - 1.f;
}

// =============================================================================
// Prologue: x[b][s][k] -> g_xT[s][grp][k][b16]  (smem transpose, coalesced)
// =============================================================================
__global__ __launch_bounds__(256)
void transpose_x(const float* __restrict__ x)
{
    __shared__ float ts[16 * 260];
    const int tid = threadIdx.x;
    const int sg  = blockIdx.x;          // s*4 + grp
    const int s   = sg >> 2, grp = sg & 3;
    const int bb  = tid >> 4, kq = tid & 15;

    const float* src = x + ((size_t)(grp * 16 + bb) * S_LEN + s) * IDIM + kq * 16;
#pragma unroll
    for (int i = 0; i < 4; i++)
        *(float4*)(ts + bb * 260 + kq * 16 + 4 * i) = *(const float4*)(src + 4 * i);
    __syncthreads();

    float* dst = g_xT + ((size_t)sg * 256 + tid) * 16;
#pragma unroll
    for (int q = 0; q < 4; q++) {
        float4 o;
        o.x = ts[(4 * q + 0) * 260 + tid];
        o.y = ts[(4 * q + 1) * 260 + tid];
        o.z = ts[(4 * q + 2) * 260 + tid];
        o.w = ts[(4 * q + 3) * 260 + tid];
        *(float4*)(dst + 4 * q) = o;
    }
}

// =============================================================================
// Tiled GEMM (output projection): C = A[M][K]*B[N][K]^T + bias (R6-measured)
// =============================================================================
template<int KDIM>
__global__ __launch_bounds__(256, 2)
void gemm_tn(const float* __restrict__ A, const float* __restrict__ B,
             const float* __restrict__ bias, float* __restrict__ C)
{
    __shared__ float As[16 * 132];
    __shared__ float Bs[16 * 132];

    const int tid = threadIdx.x;
    const int m0 = blockIdx.y * 128;
    const int n0 = blockIdx.x * 128;
    const int lr = tid >> 2;
    const int lc = tid & 3;
    const int tx = tid & 15;
    const int ty = tid >> 4;

    const float* Ap = A + (size_t)(m0 + lr) * KDIM + lc * 4;
    const float* Bp = B + (size_t)(n0 + lr) * KDIM + lc * 4;

    float2 c2[8][4];
#pragma unroll
    for (int i = 0; i < 8; i++)
#pragma unroll
        for (int j = 0; j < 4; j++) c2[i][j] = make_float2(0.f, 0.f);

    float4 pa0 = *(const float4*)(Ap);
    float4 pa1 = *(const float4*)(Ap + (size_t)64 * KDIM);
    float4 pb0 = *(const float4*)(Bp);
    float4 pb1 = *(const float4*)(Bp + (size_t)64 * KDIM);

    const int KT = KDIM / 16;
    for (int kt = 0; kt < KT; kt++) {
        {
            const float* a0 = (const float*)&pa0;
            const float* a1 = (const float*)&pa1;
            const float* b0 = (const float*)&pb0;
            const float* b1 = (const float*)&pb1;
#pragma unroll
            for (int j = 0; j < 4; j++) {
                As[(lc * 4 + j) * 132 + lr]      = a0[j];
                As[(lc * 4 + j) * 132 + lr + 64] = a1[j];
                Bs[(lc * 4 + j) * 132 + lr]      = b0[j];
                Bs[(lc * 4 + j) * 132 + lr + 64] = b1[j];
            }
        }
        __syncthreads();
        if (kt + 1 < KT) {
            Ap += 16; Bp += 16;
            pa0 = *(const float4*)(Ap);
            pa1 = *(const float4*)(Ap + (size_t)64 * KDIM);
            pb0 = *(const float4*)(Bp);
            pb1 = *(const float4*)(Bp + (size_t)64 * KDIM);
        }
#pragma unroll
        for (int k = 0; k < 16; k++) {
            float4 a0 = *(const float4*)&As[k * 132 + ty * 4];
            float4 a1 = *(const float4*)&As[k * 132 + 64 + ty * 4];
            float4 b0 = *(const float4*)&Bs[k * 132 + tx * 4];
            float4 b1 = *(const float4*)&Bs[k * 132 + 64 + tx * 4];
            float av[8] = {a0.x, a0.y, a0.z, a0.w, a1.x, a1.y, a1.z, a1.w};
            float2 bv[4] = {{b0.x, b0.y}, {b0.z, b0.w}, {b1.x, b1.y}, {b1.z, b1.w}};
#pragma unroll
            for (int i = 0; i < 8; i++) {
                float2 ad = make_float2(av[i], av[i]);
#pragma unroll
                for (int j = 0; j < 4; j++) c2[i][j] = ffma2(ad, bv[j], c2[i][j]);
            }
        }
        __syncthreads();
    }

    int ncol[4];
    float2 bb[4];
#pragma unroll
    for (int j = 0; j < 4; j++) {
        ncol[j] = n0 + ((j < 2) ? (tx * 4 + 2 * j) : (64 + tx * 4 + 2 * (j - 2)));
        bb[j] = make_float2(bias[ncol[j]], bias[ncol[j] + 1]);
    }

#pragma unroll
    for (int i = 0; i < 8; i++) {
        int r = m0 + ((i < 4) ? (ty * 4 + i) : (64 + ty * 4 + (i - 4)));
        int s = r >> 6, b = r & 63;                 // r = s*64+b
        size_t rbase = ((size_t)(b * S_LEN + s)) * ODIM;
#pragma unroll
        for (int j = 0; j < 4; j++) {
            float2 v = make_float2(c2[i][j].x + bb[j].x, c2[i][j].y + bb[j].y);
            *(float2*)&C[rbase + ncol[j]] = v;
        }
    }
}

// =============================================================================
// Fused GRU scan (R6 structure + cp.async staging). 4 groups x 32 CTAs;
// slice = 16 j; w_hh register-resident, w_ih SMEM. Warp-parallel exchange:
// warp w polls block-w counter then cp.asyncs its 4KB; gi chunk B hides the
// async latency. 3 bars/step. Spill-free (~190 regs).
// =============================================================================
__global__ __launch_bounds__(256, 1)
void gru_scan(const float* __restrict__ w_ih, const float* __restrict__ w_hh,
              const float* __restrict__ b_ih, const float* __restrict__ b_hh)
{
    extern __shared__ float sm[];
    float* sh_h = sm;                      // 8192 f : h [k512][b16]
    float* sred = sm + 8192;               // 17408 f: partials 256 x RSTR
    float* sx   = sm + 8192 + 17408;       // 8192 f : x tiles, 2 x [k256][b16]
    float* sw   = sx + 8192;               // 12336 f: w_ih slice [48][257]

    const uint32_t sh_h_u = (uint32_t)__cvta_generic_to_shared(sh_h);
    const uint32_t sx_u   = (uint32_t)__cvta_generic_to_shared(sx);

    const int tid     = threadIdx.x;
    const int lane    = tid & 31;
    const int wrp     = tid >> 5;          // warp id = exchange block id
    const int grp     = blockIdx.x >> 5;
    const int slice   = blockIdx.x & 31;
    const int j0      = slice * 16;
    const int b0      = grp * 16;
    const int own_blk = slice >> 2;
    const int kI      = tid >> 4;          // k-chunk id 0..15
    const int jI      = tid & 15;          // hidden unit in slice
    const int jj      = kI;                // gate-stage hidden idx
    const int bbat    = jI;                // gate-stage batch idx

    // ---- w_hh register-resident (k = kI + 16*m) ----------------------------
    float w[3][32];
#pragma unroll
    for (int g = 0; g < 3; g++) {
        const float* p = w_hh + (size_t)(g * HID + j0 + jI) * HID + kI;
#pragma unroll
        for (int m = 0; m < 32; m++) w[g][m] = p[16 * m];
    }

    // ---- stage w_ih slice into SMEM (rows (g,j), pad 257) ------------------
    for (int i = tid; i < 48 * 256; i += 256) {
        int row = i >> 8, k = i & 255;
        int g = row >> 4, jr = row & 15;
        sw[row * 257 + k] = w_ih[(size_t)(g * HID + j0 + jr) * IDIM + k];
    }

    // ---- fused biases ------------------------------------------------------
    const float bR  = b_ih[j0 + jj]           + b_hh[j0 + jj];
    const float bZ  = b_ih[HID + j0 + jj]     + b_hh[HID + j0 + jj];
    const float bIN = b_ih[2 * HID + j0 + jj];
    const float bHN = b_hh[2 * HID + j0 + jj];

    for (int i = tid; i < 8192; i += 256) sh_h[i] = 0.f;   // h_0 = 0
    {   // stage x tile for step 0
        const float4* src = (const float4*)(g_xT + (size_t)grp * 4096);
        float4* dst = (float4*)sx;
#pragma unroll
        for (int i = 0; i < 4; i++) dst[tid + 256 * i] = src[tid + 256 * i];
    }
    __syncthreads();

    for (int s = 0; s < S_LEN; s++) {
        float2 acc[8][4];
#pragma unroll
        for (int p = 0; p < 8; p++)
#pragma unroll
            for (int g = 0; g < 4; g++) acc[p][g] = make_float2(0.f, 0.f);

        const float* xrow = sx + (s & 1) * 4096 + kI * 256;
        const float* swr = sw + jI * 257        + kI * 16;
        const float* swz = sw + (16 + jI) * 257 + kI * 16;
        const float* swn = sw + (32 + jI) * 257 + kI * 16;

        // ---- gi chunk A (kk 0..7) -----------------------------------------
#pragma unroll 4
        for (int kk = 0; kk < 8; kk++) {
            float2 WR = {swr[kk], swr[kk]}, WZ = {swz[kk], swz[kk]}, WN = {swn[kk], swn[kk]};
            const float* xr = xrow + kk * 16;
#pragma unroll
            for (int q = 0; q < 4; q++) {
                float4 x4 = *(const float4*)(xr + 4 * q);
                float2 x01 = {x4.x, x4.y}, x23 = {x4.z, x4.w};
                acc[2 * q][0]     = ffma2(x01, WR, acc[2 * q][0]);
                acc[2 * q][1]     = ffma2(x01, WZ, acc[2 * q][1]);
                acc[2 * q][3]     = ffma2(x01, WN, acc[2 * q][3]);
                acc[2 * q + 1][0] = ffma2(x23, WR, acc[2 * q + 1][0]);
                acc[2 * q + 1][1] = ffma2(x23, WZ, acc[2 * q + 1][1]);
                acc[2 * q + 1][3] = ffma2(x23, WN, acc[2 * q + 1][3]);
            }
        }

        // ---- poll + cp.async h block (no register staging) -----------------
        if (s > 0) {
            if (lane == 0) poll_ge(&g_blk[(grp * 8 + wrp) * 64], 4u * (unsigned)s);
            __syncwarp();
            const float4* srcb = (const float4*)(g_hsT + ((size_t)s * 4 + grp) * 8192)
                                 + wrp * 256 + lane;
            uint32_t d = sh_h_u + (uint32_t)(wrp * 256 + lane) * 16;
#pragma unroll
            for (int i = 0; i < 8; i++)
                cp_async16(d + (uint32_t)i * 32 * 16, srcb + 32 * i);
            CP_COMMIT();
        }

        // ---- gi chunk B (kk 8..15) — hides cp.async latency ----------------
#pragma unroll 4
        for (int kk = 8; kk < 16; kk++) {
            float2 WR = {swr[kk], swr[kk]}, WZ = {swz[kk], swz[kk]}, WN = {swn[kk], swn[kk]};
            const float* xr = xrow + kk * 16;
#pragma unroll
            for (int q = 0; q < 4; q++) {
                float4 x4 = *(const float4*)(xr + 4 * q);
                float2 x01 = {x4.x, x4.y}, x23 = {x4.z, x4.w};
                acc[2 * q][0]     = ffma2(x01, WR, acc[2 * q][0]);
                acc[2 * q][1]     = ffma2(x01, WZ, acc[2 * q][1]);
                acc[2 * q][3]     = ffma2(x01, WN, acc[2 * q][3]);
                acc[2 * q + 1][0] = ffma2(x23, WR, acc[2 * q + 1][0]);
                acc[2 * q + 1][1] = ffma2(x23, WZ, acc[2 * q + 1][1]);
                acc[2 * q + 1][3] = ffma2(x23, WN, acc[2 * q + 1][3]);
            }
        }

        if (s > 0) CP_WAIT0();
        __syncthreads();                                          // bar1

        // ---- gh-FMA over full 512 k (planes 0,1,2) -------------------------
        if (s > 0) {
#pragma unroll
            for (int m = 0; m < 32; m++) {
                const float* hr = sh_h + (kI + 16 * m) * 16;
                float2 WR = {w[0][m], w[0][m]};
                float2 WZ = {w[1][m], w[1][m]};
                float2 WN = {w[2][m], w[2][m]};
#pragma unroll
                for (int q = 0; q < 4; q++) {
                    float4 h4v = *(const float4*)(hr + 4 * q);
                    float2 h01 = {h4v.x, h4v.y}, h23 = {h4v.z, h4v.w};
                    acc[2 * q][0]     = ffma2(h01, WR, acc[2 * q][0]);
                    acc[2 * q][1]     = ffma2(h01, WZ, acc[2 * q][1]);
                    acc[2 * q][2]     = ffma2(h01, WN, acc[2 * q][2]);
                    acc[2 * q + 1][0] = ffma2(h23, WR, acc[2 * q + 1][0]);
                    acc[2 * q + 1][1] = ffma2(h23, WZ, acc[2 * q + 1][1]);
                    acc[2 * q + 1][2] = ffma2(h23, WN, acc[2 * q + 1][2]);
                }
            }
        }

        // ---- dump: 16 waste-free STS.128 -----------------------------------
        {
            float* rp = sred + tid * RSTR;
#pragma unroll
            for (int p = 0; p < 8; p++) {
                *(float4*)(rp + 8 * p)     =
                    make_float4(acc[p][0].x, acc[p][1].x, acc[p][2].x, acc[p][3].x);
                *(float4*)(rp + 8 * p + 4) =
                    make_float4(acc[p][0].y, acc[p][1].y, acc[p][2].y, acc[p][3].y);
            }
        }
        __syncthreads();                                          // bar2

        // ---- x(s+1) prefetch straight to SMEM via cp.async -----------------
        if (s + 1 < S_LEN) {
            const float4* xsrc = (const float4*)(g_xT + ((size_t)(s + 1) * 4 + grp) * 4096);
            uint32_t d = sx_u + (uint32_t)(((s + 1) & 1) * 4096 + tid * 4) * 4;
#pragma unroll
            for (int i = 0; i < 4; i++)
                cp_async16(d + (uint32_t)i * 256 * 16, xsrc + tid + 256 * i);
            CP_COMMIT();
        }

        // ---- reduce + gates + stores ---------------------------------------
        {
            float R = bR, Z = bZ, GN = 0.f, GI = bIN;
#pragma unroll
            for (int kc = 0; kc < 16; kc++) {
                float4 v = *(const float4*)(sred + (kc * 16 + jj) * RSTR + 4 * bbat);
                R += v.x; Z += v.y; GN += v.z; GI += v.w;
            }
            float r = fast_sigmoid(R);
            float z = fast_sigmoid(Z);
            float n = fast_tanh(GI + r * (GN + bHN));
            float hp = sh_h[(j0 + jj) * 16 + bbat];
            float hn = (1.f - z) * n + z * hp;

            // exchange write (peers consume next step) + GEMM2 layout write
            g_hsT[((size_t)(s + 1) * 4 + grp) * 8192 + (j0 + jj) * 16 + bbat] = hn;
            g_hs[((size_t)s * BATCH + b0 + bbat) * HID + j0 + jj] = hn;
        }

        if (s + 1 < S_LEN) CP_WAIT0();   // x tile landed
        __syncthreads();                                          // bar3

        if (tid == 0) {
            unsigned* ctr = &g_blk[(grp * 8 + own_blk) * 64];
            asm volatile("red.release.gpu.global.add.u32 [%0], 1;" :: "l"(ctr) : "memory");
        }
    }
}

// =============================================================================
extern "C" void kernel_launch(void* const* d_in, const int* in_sizes, int n_in,
                              void* d_out, int out_size)
{
    (void)in_sizes; (void)n_in; (void)out_size;
    const float* x     = (const float*)d_in[0];
    const float* w_ih  = (const float*)d_in[1];
    const float* w_hh  = (const float*)d_in[2];
    const float* b_ih  = (const float*)d_in[3];
    const float* b_hh  = (const float*)d_in[4];
    const float* w_out = (const float*)d_in[5];
    const float* b_out = (const float*)d_in[6];
    float* out = (float*)d_out;

    void *p_hs = nullptr, *p_blk = nullptr;
    cudaGetSymbolAddress(&p_hs, g_hs);
    cudaGetSymbolAddress(&p_blk, g_blk);

    cudaMemsetAsync(p_blk, 0, sizeof(unsigned) * 4 * 8 * 64);

    const int scan_smem = (8192 + 256 * RSTR + 8192 + 48 * 257) * 4;   // 184512 B
    cudaFuncSetAttribute(gru_scan, cudaFuncAttributeMaxDynamicSharedMemorySize, scan_smem);

    // Phase 0: transpose x into [s][grp][k][b16]
    transpose_x<<<S_LEN * 4, 256>>>(x);

    // Phase 1+2: fused GRU scan (gi in-step), cp.async staging
    gru_scan<<<128, 256, scan_smem>>>(w_ih, w_hh, b_ih, b_hh);

    // Phase 3: out = hs @ w_out^T + b_out   (M=32768, N=512, K=512)
    gemm_tn<HID><<<dim3(ODIM / 128, (BATCH * S_LEN) / 128), 256>>>(
        (const float*)p_hs, w_out, b_out, out);
}